// round 5
// baseline (speedup 1.0000x reference)
#include <cuda_runtime.h>
#include <stdint.h>

#define PI_F 3.14159265358979323846f
#define F0C  0.91f
#define NL   512      // EH*EW
#define EHc  16
#define EWc  32
#define C16PI 5.092958178940651f   // 16/pi

// ---------------------------------------------------------------------------
__global__ void base_merge_kernel(const float* __restrict__ grd_rgb,
                                  const float* __restrict__ grd_acc,
                                  float* __restrict__ out, int n3)
{
    int j = blockIdx.x * blockDim.x + threadIdx.x;
    if (j < n3) {
        float a = grd_acc[j / 3];
        out[j] = grd_rgb[j] * a;
    }
}

// ---------------------------------------------------------------------------
__device__ __forceinline__ float lin2srgb(float x)
{
    x = __saturatef(x);
    if (x <= 0.0031308f) return 12.92f * x;
    return 1.055f * powf(fmaxf(x, 1e-8f), 1.0f / 2.4f) - 0.055f;
}

__device__ __forceinline__ float fsqrt_approx(float x)
{
    float r;
    asm("sqrt.approx.f32 %0, %1;" : "=f"(r) : "f"(x));
    return r;
}

// acos(z) * 16/pi, |err| ~ 1e-7 v-units. A&S 4.4.46 with coefficients
// pre-scaled by 16/pi.
__device__ __forceinline__ float acos_v_units(float z)
{
    const float az = fabsf(z);
    float p = fmaf(az, -0.00642981f, 0.03397048f);
    p = fmaf(az, p, -0.08702909f);
    p = fmaf(az, p,  0.15733105f);
    p = fmaf(az, p, -0.25553564f);
    p = fmaf(az, p,  0.45316617f);
    p = fmaf(az, p, -1.09294276f);
    p = fmaf(az, p,  8.0f);
    const float sp = fsqrt_approx(1.0f - az) * p;
    return (z >= 0.0f) ? sp : 16.0f - sp;
}

// atan2(y,x) * 16/pi (result may be shifted by a multiple of 32 at the +-pi
// seam; caller wraps u mod 32 so this is harmless). |err| ~ 5e-6 u-units.
__device__ __forceinline__ float atan2_u_units(float y, float x)
{
    const float ax = fabsf(x), ay = fabsf(y);
    const float mx = fmaxf(ax, ay), mn = fminf(ax, ay);
    float t = __fdividef(mn, mx);
    t = (mx > 0.0f) ? t : 0.0f;
    const float s = t * t;
    float p = fmaf(s, -0.05969558f, 0.26816104f);
    p = fmaf(s, p, -0.59298770f);
    p = fmaf(s, p,  0.98571024f);
    p = fmaf(s, p, -1.69403920f);
    p = fmaf(s, p,  5.09284237f);
    float r = t * p;                       // atan(mn/mx) in u-units, [0,4]
    if (ay > ax)    r = 8.0f  - r;
    if (x  < 0.0f)  r = 16.0f - r;
    return (y < 0.0f) ? -r : r;
}

// ---------------------------------------------------------------------------
// One warp per surface point; lanes stride the 512 lights.
// ---------------------------------------------------------------------------
__global__ __launch_bounds__(256)
void render_kernel(const float* __restrict__ surf,
                   const float* __restrict__ ray_o,
                   const float* __restrict__ norm_raw,
                   const float* __restrict__ albedo,
                   const float* __restrict__ rough,
                   const float* __restrict__ lvis,
                   const float* __restrict__ xyz,
                   const float* __restrict__ area,
                   const float* __restrict__ probe,
                   const float* __restrict__ grd_rgb,
                   const float* __restrict__ grd_acc,
                   const int*   __restrict__ inds,
                   float* __restrict__ out,
                   int P)
{
    __shared__ float4 s_xyz  [NL];   // light position (w unused)
    __shared__ float4 s_ldira[NL];   // normalized light dir + area in .w
    __shared__ float4 s_probe[NL];   // probe rgb (w unused)

    for (int i = threadIdx.x; i < NL; i += blockDim.x) {
        float x = xyz[i * 3 + 0], y = xyz[i * 3 + 1], z = xyz[i * 3 + 2];
        s_xyz[i]   = make_float4(x, y, z, 0.0f);
        s_probe[i] = make_float4(probe[i * 3 + 0], probe[i * 3 + 1],
                                 probe[i * 3 + 2], 0.0f);
        float inv = __fdividef(1.0f, sqrtf(x * x + y * y + z * z) + 1e-8f);
        s_ldira[i] = make_float4(x * inv, y * inv, z * inv, area[i]);
    }
    __syncthreads();

    const int warp = threadIdx.x >> 5;
    const int lane = threadIdx.x & 31;
    const int p = blockIdx.x * (blockDim.x >> 5) + warp;
    if (p >= P) return;

    // ---- per-point invariants ----
    const float sx = surf[p * 3 + 0], sy = surf[p * 3 + 1], sz = surf[p * 3 + 2];

    float nx = norm_raw[p * 3 + 0], ny = norm_raw[p * 3 + 1], nz = norm_raw[p * 3 + 2];
    {
        float inv = __fdividef(1.0f, sqrtf(nx * nx + ny * ny + nz * nz) + 1e-8f);
        nx *= inv; ny *= inv; nz *= inv;
    }
    float cx = ray_o[p * 3 + 0] - sx, cy = ray_o[p * 3 + 1] - sy, cz = ray_o[p * 3 + 2] - sz;
    {
        float inv = __fdividef(1.0f, sqrtf(cx * cx + cy * cy + cz * cz) + 1e-8f);
        cx *= inv; cy *= inv; cz *= inv;
    }

    const float cos_v = nx * cx + ny * cy + nz * cz;
    const float acv   = fabsf(cos_v);
    const float r     = rough[p];
    const float a     = r * r;
    const float a2    = a * a;
    const float a2opi = a2 * (1.0f / PI_F);
    const float a2m1  = a2 - 1.0f;

    float cvs  = fminf(cos_v * cos_v, 1.0f);
    float tanv = (cvs > 1e-12f) ? __fdividef(1.0f - cvs, cvs) : 0.0f;
    tanv       = fminf(tanv, 1e10f);
    const float g0 = __fdividef(2.0f, 1.0f + sqrtf(1.0f + a2 * tanv));

    const float aopR = albedo[p * 3 + 0] * (1.0f / PI_F);
    const float aopG = albedo[p * 3 + 1] * (1.0f / PI_F);
    const float aopB = albedo[p * 3 + 2] * (1.0f / PI_F);

    float accR = 0.0f, accG = 0.0f, accB = 0.0f;
    const float* __restrict__ lvp = lvis + (size_t)p * NL;

    #pragma unroll 4
    for (int li = lane; li < NL; li += 32) {
        const float lv = lvp[li];

        const float4 lp = s_xyz[li];
        float lx = lp.x - sx, ly = lp.y - sy, lz = lp.z - sz;
        const float invl = rsqrtf(lx * lx + ly * ly + lz * lz);
        lx *= invl; ly *= invl; lz *= invl;

        // --- envmap bilinear sample (custom trig, directly in texel units) ---
        const float zz = fminf(fmaxf(lz, -1.0f + 1e-6f), 1.0f - 1e-6f);
        const float v  = acos_v_units(zz) - 0.5f;
        const float u  = atan2_u_units(ly, lx) + 15.5f;

        const float v0f = floorf(v), u0f = floorf(u);
        const float fv = v - v0f, fu = u - u0f;
        int v0 = (int)v0f; v0 = v0 < 0 ? 0 : v0;
        int v1 = v0 + 1;   v1 = v1 > (EHc - 1) ? (EHc - 1) : v1;
        const int u0 = ((int)u0f + EWc) & (EWc - 1);
        const int u1 = (u0 + 1) & (EWc - 1);
        const float4 p00 = s_probe[v0 * EWc + u0];
        const float4 p01 = s_probe[v0 * EWc + u1];
        const float4 p10 = s_probe[v1 * EWc + u0];
        const float4 p11 = s_probe[v1 * EWc + u1];
        const float w00 = (1.0f - fu) * (1.0f - fv);
        const float w01 = fu * (1.0f - fv);
        const float w10 = (1.0f - fu) * fv;
        const float w11 = fu * fv;
        const float LR = p00.x * w00 + p01.x * w01 + p10.x * w10 + p11.x * w11;
        const float LG = p00.y * w00 + p01.y * w01 + p10.y * w10 + p11.y * w11;
        const float LB = p00.z * w00 + p01.z * w01 + p10.z * w10 + p11.z * w11;

        const float4 lda = s_ldira[li];
        const float ldot = lda.x * nx + lda.y * ny + lda.z * nz;

        // --- microfacet BRDF ---
        float hx = lx + cx, hy = ly + cy, hz = lz + cz;
        const float invh = __fdividef(1.0f, sqrtf(hx * hx + hy * hy + hz * hz) + 1e-8f);
        hx *= invh; hy *= invh; hz *= invh;

        const float ldh = lx * hx + ly * hy + lz * hz;
        const float t   = 1.0f - ldh;
        const float t2  = t * t;
        const float f   = F0C + (1.0f - F0C) * (t2 * t2 * t);

        const float cm  = hx * nx + hy * ny + hz * nz;
        const float cms = cm * cm;
        const float w   = fmaf(cms, a2m1, 1.0f);
        const float d   = (cm > 0.0f && cms > 1e-12f) ? __fdividef(a2opi, w * w) : 0.0f;

        const float chv = hx * cx + hy * cy + hz * cz;
        const float g   = (chv * cos_v > 0.0f) ? g0 : 0.0f;

        const float ldn = lx * nx + ly * ny + lz * nz;
        const float den = 4.0f * fabsf(ldn) * acv;
        const float micro = (den > 1e-12f) ? __fdividef(f * g * d, den) : 0.0f;

        const float s = lv * ldot * lda.w;
        accR = fmaf(micro + aopR, s * LR, accR);
        accG = fmaf(micro + aopG, s * LG, accG);
        accB = fmaf(micro + aopB, s * LB, accB);
    }

    // warp reduce
    #pragma unroll
    for (int off = 16; off; off >>= 1) {
        accR += __shfl_xor_sync(0xffffffffu, accR, off);
        accG += __shfl_xor_sync(0xffffffffu, accG, off);
        accB += __shfl_xor_sync(0xffffffffu, accB, off);
    }

    if (lane == 0) {
        const int ind = inds[p];
        const bool last = (p == P - 1) || (inds[p + 1] != ind);
        if (last) {
            const float ac   = grd_acc[ind];
            const float omac = 1.0f - ac;
            out[ind * 3 + 0] = grd_rgb[ind * 3 + 0] * ac + lin2srgb(accR) * omac;
            out[ind * 3 + 1] = grd_rgb[ind * 3 + 1] * ac + lin2srgb(accG) * omac;
            out[ind * 3 + 2] = grd_rgb[ind * 3 + 2] * ac + lin2srgb(accB) * omac;
        }
    }
}

// ---------------------------------------------------------------------------
extern "C" void kernel_launch(void* const* d_in, const int* in_sizes, int n_in,
                              void* d_out, int out_size)
{
    const float* surf     = (const float*)d_in[0];
    const float* ray_o    = (const float*)d_in[1];
    const float* norm_raw = (const float*)d_in[2];
    const float* albedo   = (const float*)d_in[3];
    const float* rough    = (const float*)d_in[4];
    const float* lvis     = (const float*)d_in[5];
    const float* xyz      = (const float*)d_in[6];
    const float* area     = (const float*)d_in[7];
    const float* probe    = (const float*)d_in[8];
    const float* grd_rgb  = (const float*)d_in[9];
    const float* grd_acc  = (const float*)d_in[10];
    const int*   inds     = (const int*)  d_in[11];
    float* out = (float*)d_out;

    const int P  = in_sizes[11];   // 8192 points
    const int n3 = out_size;       // 65536*3

    base_merge_kernel<<<(n3 + 255) / 256, 256>>>(grd_rgb, grd_acc, out, n3);

    const int warpsPerBlock = 8;
    const int blocks = (P + warpsPerBlock - 1) / warpsPerBlock;
    render_kernel<<<blocks, 256>>>(surf, ray_o, norm_raw, albedo, rough, lvis,
                                   xyz, area, probe, grd_rgb, grd_acc, inds,
                                   out, P);
}

// round 6
// speedup vs baseline: 1.5548x; 1.5548x over previous
#include <cuda_runtime.h>
#include <stdint.h>

#define PI_F 3.14159265358979323846f
#define F0C  0.91f
#define NL   512      // EH*EW
#define EHc  16
#define EWc  32

// ---------------------------------------------------------------------------
__global__ void base_merge_kernel(const float* __restrict__ grd_rgb,
                                  const float* __restrict__ grd_acc,
                                  float* __restrict__ out, int n3)
{
    int j = blockIdx.x * blockDim.x + threadIdx.x;
    if (j < n3) {
        float a = grd_acc[j / 3];
        out[j] = grd_rgb[j] * a;
    }
}

// ---------------------------------------------------------------------------
__device__ __forceinline__ float lin2srgb(float x)
{
    x = __saturatef(x);
    if (x <= 0.0031308f) return 12.92f * x;
    return 1.055f * powf(fmaxf(x, 1e-8f), 1.0f / 2.4f) - 0.055f;
}

__device__ __forceinline__ float fsqrt_approx(float x)
{
    float r;
    asm("sqrt.approx.f32 %0, %1;" : "=f"(r) : "f"(x));
    return r;
}

// acos(z) * 16/pi, |err| ~ 1e-7 v-units. A&S 4.4.46 pre-scaled by 16/pi.
__device__ __forceinline__ float acos_v_units(float z)
{
    const float az = fabsf(z);
    float p = fmaf(az, -0.00642981f, 0.03397048f);
    p = fmaf(az, p, -0.08702909f);
    p = fmaf(az, p,  0.15733105f);
    p = fmaf(az, p, -0.25553564f);
    p = fmaf(az, p,  0.45316617f);
    p = fmaf(az, p, -1.09294276f);
    p = fmaf(az, p,  8.0f);
    const float sp = fsqrt_approx(1.0f - az) * p;
    return (z >= 0.0f) ? sp : 16.0f - sp;
}

// atan2(y,x) * 16/pi (may differ by multiple of 32 at the +-pi seam; the
// caller wraps u mod 32). |err| ~ 5e-6 u-units.
__device__ __forceinline__ float atan2_u_units(float y, float x)
{
    const float ax = fabsf(x), ay = fabsf(y);
    const float mx = fmaxf(ax, ay), mn = fminf(ax, ay);
    float t = __fdividef(mn, mx);
    t = (mx > 0.0f) ? t : 0.0f;
    const float s = t * t;
    float p = fmaf(s, -0.05969558f, 0.26816104f);
    p = fmaf(s, p, -0.59298770f);
    p = fmaf(s, p,  0.98571024f);
    p = fmaf(s, p, -1.69403920f);
    p = fmaf(s, p,  5.09284237f);
    float r = t * p;                       // atan(mn/mx) in u-units, [0,4]
    if (ay > ax)    r = 8.0f  - r;
    if (x  < 0.0f)  r = 16.0f - r;
    return (y < 0.0f) ? -r : r;
}

// ---------------------------------------------------------------------------
// One warp per surface point; lanes stride the 512 lights.
// ---------------------------------------------------------------------------
__global__ __launch_bounds__(256)
void render_kernel(const float* __restrict__ surf,
                   const float* __restrict__ ray_o,
                   const float* __restrict__ norm_raw,
                   const float* __restrict__ albedo,
                   const float* __restrict__ rough,
                   const float* __restrict__ lvis,
                   const float* __restrict__ xyz,
                   const float* __restrict__ area,
                   const float* __restrict__ probe,
                   const float* __restrict__ grd_rgb,
                   const float* __restrict__ grd_acc,
                   const int*   __restrict__ inds,
                   float* __restrict__ out,
                   int P)
{
    __shared__ float4 s_xyz  [NL];       // light position (sequential access)
    __shared__ float4 s_ldira[NL];       // normalized light dir + area
    __shared__ float  s_probe[NL * 3];   // stride-3: odd stride -> all banks

    for (int i = threadIdx.x; i < NL * 3; i += blockDim.x)
        s_probe[i] = probe[i];
    for (int i = threadIdx.x; i < NL; i += blockDim.x) {
        float x = xyz[i * 3 + 0], y = xyz[i * 3 + 1], z = xyz[i * 3 + 2];
        s_xyz[i] = make_float4(x, y, z, 0.0f);
        float inv = __fdividef(1.0f, sqrtf(x * x + y * y + z * z) + 1e-8f);
        s_ldira[i] = make_float4(x * inv, y * inv, z * inv, area[i]);
    }
    __syncthreads();

    const int warp = threadIdx.x >> 5;
    const int lane = threadIdx.x & 31;
    const int p = blockIdx.x * (blockDim.x >> 5) + warp;
    if (p >= P) return;

    // ---- per-point invariants ----
    const float sx = surf[p * 3 + 0], sy = surf[p * 3 + 1], sz = surf[p * 3 + 2];

    float nx = norm_raw[p * 3 + 0], ny = norm_raw[p * 3 + 1], nz = norm_raw[p * 3 + 2];
    {
        float inv = __fdividef(1.0f, sqrtf(nx * nx + ny * ny + nz * nz) + 1e-8f);
        nx *= inv; ny *= inv; nz *= inv;
    }
    float cx = ray_o[p * 3 + 0] - sx, cy = ray_o[p * 3 + 1] - sy, cz = ray_o[p * 3 + 2] - sz;
    {
        float inv = __fdividef(1.0f, sqrtf(cx * cx + cy * cy + cz * cz) + 1e-8f);
        cx *= inv; cy *= inv; cz *= inv;
    }

    const float cos_v = nx * cx + ny * cy + nz * cz;
    const float acv   = fabsf(cos_v);
    const float r     = rough[p];
    const float a     = r * r;
    const float a2    = a * a;
    const float a2m1  = a2 - 1.0f;

    float cvs  = fminf(cos_v * cos_v, 1.0f);
    float tanv = (cvs > 1e-12f) ? __fdividef(1.0f - cvs, cvs) : 0.0f;
    tanv       = fminf(tanv, 1e10f);
    const float g0 = __fdividef(2.0f, 1.0f + sqrtf(1.0f + a2 * tanv));
    // combined numerator constant: g0 * a2/pi
    const float g0a2opi = g0 * a2 * (1.0f / PI_F);

    const float aopR = albedo[p * 3 + 0] * (1.0f / PI_F);
    const float aopG = albedo[p * 3 + 1] * (1.0f / PI_F);
    const float aopB = albedo[p * 3 + 2] * (1.0f / PI_F);

    float accR = 0.0f, accG = 0.0f, accB = 0.0f;
    const float* __restrict__ lvp = lvis + (size_t)p * NL;

    #pragma unroll 4
    for (int li = lane; li < NL; li += 32) {
        const float lv = lvp[li];

        const float4 lp = s_xyz[li];
        float lx = lp.x - sx, ly = lp.y - sy, lz = lp.z - sz;
        const float invl = rsqrtf(lx * lx + ly * ly + lz * lz);
        lx *= invl; ly *= invl; lz *= invl;

        // --- envmap bilinear sample (custom trig, direct texel units) ---
        const float zz = fminf(fmaxf(lz, -1.0f + 1e-6f), 1.0f - 1e-6f);
        const float v  = acos_v_units(zz) - 0.5f;
        const float u  = atan2_u_units(ly, lx) + 15.5f;

        const float v0f = floorf(v), u0f = floorf(u);
        const float fv = v - v0f, fu = u - u0f;
        int v0 = (int)v0f; v0 = v0 < 0 ? 0 : v0;
        int v1 = v0 + 1;   v1 = v1 > (EHc - 1) ? (EHc - 1) : v1;
        const int u0 = ((int)u0f + EWc) & (EWc - 1);
        const int u1 = (u0 + 1) & (EWc - 1);
        const float* P00 = s_probe + (v0 * EWc + u0) * 3;
        const float* P01 = s_probe + (v0 * EWc + u1) * 3;
        const float* P10 = s_probe + (v1 * EWc + u0) * 3;
        const float* P11 = s_probe + (v1 * EWc + u1) * 3;
        const float w00 = (1.0f - fu) * (1.0f - fv);
        const float w01 = fu * (1.0f - fv);
        const float w10 = (1.0f - fu) * fv;
        const float w11 = fu * fv;
        const float LR = P00[0] * w00 + P01[0] * w01 + P10[0] * w10 + P11[0] * w11;
        const float LG = P00[1] * w00 + P01[1] * w01 + P10[1] * w10 + P11[1] * w11;
        const float LB = P00[2] * w00 + P01[2] * w01 + P10[2] * w10 + P11[2] * w11;

        const float4 lda = s_ldira[li];
        const float ldot = lda.x * nx + lda.y * ny + lda.z * nz;

        // --- microfacet BRDF (single fused division) ---
        float hx = lx + cx, hy = ly + cy, hz = lz + cz;
        const float invh = __fdividef(1.0f, sqrtf(hx * hx + hy * hy + hz * hz) + 1e-8f);
        hx *= invh; hy *= invh; hz *= invh;

        const float ldh = lx * hx + ly * hy + lz * hz;
        const float t   = 1.0f - ldh;
        const float t2  = t * t;
        const float f   = F0C + (1.0f - F0C) * (t2 * t2 * t);

        const float cm  = hx * nx + hy * ny + hz * nz;
        const float cms = cm * cm;
        const float w   = fmaf(cms, a2m1, 1.0f);

        const float chv = hx * cx + hy * cy + hz * cz;
        const float ldn = lx * nx + ly * ny + lz * nz;
        const float den = 4.0f * fabsf(ldn) * acv;

        const bool ok = (cm > 0.0f) & (cms > 1e-12f) & (den > 1e-12f)
                        & (chv * cos_v > 0.0f);
        const float micro = ok ? __fdividef(f * g0a2opi, (w * w) * den) : 0.0f;

        const float s = lv * ldot * lda.w;
        accR = fmaf(micro + aopR, s * LR, accR);
        accG = fmaf(micro + aopG, s * LG, accG);
        accB = fmaf(micro + aopB, s * LB, accB);
    }

    // warp reduce
    #pragma unroll
    for (int off = 16; off; off >>= 1) {
        accR += __shfl_xor_sync(0xffffffffu, accR, off);
        accG += __shfl_xor_sync(0xffffffffu, accG, off);
        accB += __shfl_xor_sync(0xffffffffu, accB, off);
    }

    if (lane == 0) {
        const int ind = inds[p];
        const bool last = (p == P - 1) || (inds[p + 1] != ind);
        if (last) {
            const float ac   = grd_acc[ind];
            const float omac = 1.0f - ac;
            out[ind * 3 + 0] = grd_rgb[ind * 3 + 0] * ac + lin2srgb(accR) * omac;
            out[ind * 3 + 1] = grd_rgb[ind * 3 + 1] * ac + lin2srgb(accG) * omac;
            out[ind * 3 + 2] = grd_rgb[ind * 3 + 2] * ac + lin2srgb(accB) * omac;
        }
    }
}

// ---------------------------------------------------------------------------
extern "C" void kernel_launch(void* const* d_in, const int* in_sizes, int n_in,
                              void* d_out, int out_size)
{
    const float* surf     = (const float*)d_in[0];
    const float* ray_o    = (const float*)d_in[1];
    const float* norm_raw = (const float*)d_in[2];
    const float* albedo   = (const float*)d_in[3];
    const float* rough    = (const float*)d_in[4];
    const float* lvis     = (const float*)d_in[5];
    const float* xyz      = (const float*)d_in[6];
    const float* area     = (const float*)d_in[7];
    const float* probe    = (const float*)d_in[8];
    const float* grd_rgb  = (const float*)d_in[9];
    const float* grd_acc  = (const float*)d_in[10];
    const int*   inds     = (const int*)  d_in[11];
    float* out = (float*)d_out;

    const int P  = in_sizes[11];   // 8192 points
    const int n3 = out_size;       // 65536*3

    base_merge_kernel<<<(n3 + 255) / 256, 256>>>(grd_rgb, grd_acc, out, n3);

    const int warpsPerBlock = 8;
    const int blocks = (P + warpsPerBlock - 1) / warpsPerBlock;
    render_kernel<<<blocks, 256>>>(surf, ray_o, norm_raw, albedo, rough, lvis,
                                   xyz, area, probe, grd_rgb, grd_acc, inds,
                                   out, P);
}

// round 10
// speedup vs baseline: 1.6464x; 1.0589x over previous
#include <cuda_runtime.h>
#include <cuda_fp16.h>
#include <stdint.h>

#define PI_F 3.14159265358979323846f
#define F0C  0.91f
#define NL   512      // EH*EW
#define EHc  16
#define EWc  32

// ---------------------------------------------------------------------------
__global__ void base_merge_kernel(const float* __restrict__ grd_rgb,
                                  const float* __restrict__ grd_acc,
                                  float* __restrict__ out, int n3)
{
    int j = blockIdx.x * blockDim.x + threadIdx.x;
    if (j < n3) {
        float a = grd_acc[j / 3];
        out[j] = grd_rgb[j] * a;
    }
}

// ---------------------------------------------------------------------------
__device__ __forceinline__ float lin2srgb(float x)
{
    x = __saturatef(x);
    if (x <= 0.0031308f) return 12.92f * x;
    return 1.055f * powf(fmaxf(x, 1e-8f), 1.0f / 2.4f) - 0.055f;
}

__device__ __forceinline__ float fsqrt_approx(float x)
{
    float r;
    asm("sqrt.approx.f32 %0, %1;" : "=f"(r) : "f"(x));
    return r;
}

// acos(z) * 16/pi, |err| ~ 1e-7 v-units. A&S 4.4.46 pre-scaled by 16/pi.
__device__ __forceinline__ float acos_v_units(float z)
{
    const float az = fabsf(z);
    float p = fmaf(az, -0.00642981f, 0.03397048f);
    p = fmaf(az, p, -0.08702909f);
    p = fmaf(az, p,  0.15733105f);
    p = fmaf(az, p, -0.25553564f);
    p = fmaf(az, p,  0.45316617f);
    p = fmaf(az, p, -1.09294276f);
    p = fmaf(az, p,  8.0f);
    const float sp = fsqrt_approx(1.0f - az) * p;
    return (z >= 0.0f) ? sp : 16.0f - sp;
}

// atan2(y,x) * 16/pi (may differ by a multiple of 32 at the +-pi seam; the
// caller wraps u mod 32). |err| ~ 5e-6 u-units.
__device__ __forceinline__ float atan2_u_units(float y, float x)
{
    const float ax = fabsf(x), ay = fabsf(y);
    const float mx = fmaxf(ax, ay), mn = fminf(ax, ay);
    float t = __fdividef(mn, mx);
    t = (mx > 0.0f) ? t : 0.0f;
    const float s = t * t;
    float p = fmaf(s, -0.05969558f, 0.26816104f);
    p = fmaf(s, p, -0.59298770f);
    p = fmaf(s, p,  0.98571024f);
    p = fmaf(s, p, -1.69403920f);
    p = fmaf(s, p,  5.09284237f);
    float r = t * p;                       // atan(mn/mx) in u-units, [0,4]
    if (ay > ax)    r = 8.0f  - r;
    if (x  < 0.0f)  r = 16.0f - r;
    return (y < 0.0f) ? -r : r;
}

// ---------------------------------------------------------------------------
// One warp per surface point; lanes stride the 512 lights.
// ---------------------------------------------------------------------------
__global__ __launch_bounds__(256)
void render_kernel(const float* __restrict__ surf,
                   const float* __restrict__ ray_o,
                   const float* __restrict__ norm_raw,
                   const float* __restrict__ albedo,
                   const float* __restrict__ rough,
                   const float* __restrict__ lvis,
                   const float* __restrict__ xyz,
                   const float* __restrict__ area,
                   const float* __restrict__ probe,
                   const float* __restrict__ grd_rgb,
                   const float* __restrict__ grd_acc,
                   const int*   __restrict__ inds,
                   float* __restrict__ out,
                   int P)
{
    // (x, y, z, invnorm*area) per light — one LDS.128, sequential access
    __shared__ float4 s_light[NL];
    // probe texel packed as {half2(r,g), half2(b,0)} — one LDS.64 per texel
    __shared__ uint2  s_probeh[NL];

    for (int i = threadIdx.x; i < NL; i += blockDim.x) {
        float x = xyz[i * 3 + 0], y = xyz[i * 3 + 1], z = xyz[i * 3 + 2];
        float inv = __fdividef(1.0f, sqrtf(x * x + y * y + z * z) + 1e-8f);
        s_light[i] = make_float4(x, y, z, inv * area[i]);

        __half2 rg = __floats2half2_rn(probe[i * 3 + 0], probe[i * 3 + 1]);
        __half2 b0 = __floats2half2_rn(probe[i * 3 + 2], 0.0f);
        s_probeh[i] = make_uint2(*(const unsigned int*)&rg,
                                 *(const unsigned int*)&b0);
    }
    __syncthreads();

    const int warp = threadIdx.x >> 5;
    const int lane = threadIdx.x & 31;
    const int p = blockIdx.x * (blockDim.x >> 5) + warp;
    if (p >= P) return;

    // ---- per-point invariants ----
    const float sx = surf[p * 3 + 0], sy = surf[p * 3 + 1], sz = surf[p * 3 + 2];

    float nx = norm_raw[p * 3 + 0], ny = norm_raw[p * 3 + 1], nz = norm_raw[p * 3 + 2];
    {
        float inv = __fdividef(1.0f, sqrtf(nx * nx + ny * ny + nz * nz) + 1e-8f);
        nx *= inv; ny *= inv; nz *= inv;
    }
    float cx = ray_o[p * 3 + 0] - sx, cy = ray_o[p * 3 + 1] - sy, cz = ray_o[p * 3 + 2] - sz;
    {
        float inv = __fdividef(1.0f, sqrtf(cx * cx + cy * cy + cz * cz) + 1e-8f);
        cx *= inv; cy *= inv; cz *= inv;
    }

    const float cos_v = nx * cx + ny * cy + nz * cz;
    const float acv   = fabsf(cos_v);
    const float r     = rough[p];
    const float a     = r * r;
    const float a2    = a * a;
    const float a2m1  = a2 - 1.0f;

    float cvs  = fminf(cos_v * cos_v, 1.0f);
    float tanv = (cvs > 1e-12f) ? __fdividef(1.0f - cvs, cvs) : 0.0f;
    tanv       = fminf(tanv, 1e10f);
    const float g0 = __fdividef(2.0f, 1.0f + sqrtf(1.0f + a2 * tanv));
    const float g0a2opi = g0 * a2 * (1.0f / PI_F);

    const float aopR = albedo[p * 3 + 0] * (1.0f / PI_F);
    const float aopG = albedo[p * 3 + 1] * (1.0f / PI_F);
    const float aopB = albedo[p * 3 + 2] * (1.0f / PI_F);

    float accR = 0.0f, accG = 0.0f, accB = 0.0f;
    const float* __restrict__ lvp = lvis + (size_t)p * NL;

    #pragma unroll 4
    for (int li = lane; li < NL; li += 32) {
        const float lv = lvp[li];

        const float4 lp = s_light[li];
        float lx = lp.x - sx, ly = lp.y - sy, lz = lp.z - sz;
        const float invl = rsqrtf(lx * lx + ly * ly + lz * lz);
        lx *= invl; ly *= invl; lz *= invl;

        // ldot * area folded: dot(xyz, n) * (invnorm*area)
        const float ldot_area = (lp.x * nx + lp.y * ny + lp.z * nz) * lp.w;

        // --- envmap bilinear sample (custom trig, direct texel units) ---
        const float zz = fminf(fmaxf(lz, -1.0f + 1e-6f), 1.0f - 1e-6f);
        const float v  = acos_v_units(zz) - 0.5f;
        const float u  = atan2_u_units(ly, lx) + 15.5f;

        const float v0f = floorf(v), u0f = floorf(u);
        const float fv = v - v0f, fu = u - u0f;
        int v0 = (int)v0f; v0 = v0 < 0 ? 0 : v0;
        int v1 = v0 + 1;   v1 = v1 > (EHc - 1) ? (EHc - 1) : v1;
        const int u0 = ((int)u0f + EWc) & (EWc - 1);
        const int u1 = (u0 + 1) & (EWc - 1);

        const uint2 t00 = s_probeh[(v0 << 5) + u0];
        const uint2 t01 = s_probeh[(v0 << 5) + u1];
        const uint2 t10 = s_probeh[(v1 << 5) + u0];
        const uint2 t11 = s_probeh[(v1 << 5) + u1];
        const float2 rg00 = __half22float2(*(const __half2*)&t00.x);
        const float2 rg01 = __half22float2(*(const __half2*)&t01.x);
        const float2 rg10 = __half22float2(*(const __half2*)&t10.x);
        const float2 rg11 = __half22float2(*(const __half2*)&t11.x);
        const float  b00  = __low2float(*(const __half2*)&t00.y);
        const float  b01  = __low2float(*(const __half2*)&t01.y);
        const float  b10  = __low2float(*(const __half2*)&t10.y);
        const float  b11  = __low2float(*(const __half2*)&t11.y);

        const float w00 = (1.0f - fu) * (1.0f - fv);
        const float w01 = fu * (1.0f - fv);
        const float w10 = (1.0f - fu) * fv;
        const float w11 = fu * fv;
        const float LR = rg00.x * w00 + rg01.x * w01 + rg10.x * w10 + rg11.x * w11;
        const float LG = rg00.y * w00 + rg01.y * w01 + rg10.y * w10 + rg11.y * w11;
        const float LB = b00   * w00 + b01   * w01 + b10   * w10 + b11   * w11;

        // --- microfacet BRDF (single fused division) ---
        float hx = lx + cx, hy = ly + cy, hz = lz + cz;
        const float invh = __fdividef(1.0f, sqrtf(hx * hx + hy * hy + hz * hz) + 1e-8f);
        hx *= invh; hy *= invh; hz *= invh;

        const float ldh = lx * hx + ly * hy + lz * hz;
        const float t   = 1.0f - ldh;
        const float t2  = t * t;
        const float f   = F0C + (1.0f - F0C) * (t2 * t2 * t);

        const float cm  = hx * nx + hy * ny + hz * nz;
        const float cms = cm * cm;
        const float w   = fmaf(cms, a2m1, 1.0f);

        const float chv = hx * cx + hy * cy + hz * cz;
        const float ldn = lx * nx + ly * ny + lz * nz;
        const float den = 4.0f * fabsf(ldn) * acv;

        const bool ok = (cm > 0.0f) & (cms > 1e-12f) & (den > 1e-12f)
                        & (chv * cos_v > 0.0f);
        const float micro = ok ? __fdividef(f * g0a2opi, (w * w) * den) : 0.0f;

        const float s = lv * ldot_area;
        accR = fmaf(micro + aopR, s * LR, accR);
        accG = fmaf(micro + aopG, s * LG, accG);
        accB = fmaf(micro + aopB, s * LB, accB);
    }

    // warp reduce
    #pragma unroll
    for (int off = 16; off; off >>= 1) {
        accR += __shfl_xor_sync(0xffffffffu, accR, off);
        accG += __shfl_xor_sync(0xffffffffu, accG, off);
        accB += __shfl_xor_sync(0xffffffffu, accB, off);
    }

    if (lane == 0) {
        const int ind = inds[p];
        const bool last = (p == P - 1) || (inds[p + 1] != ind);
        if (last) {
            const float ac   = grd_acc[ind];
            const float omac = 1.0f - ac;
            out[ind * 3 + 0] = grd_rgb[ind * 3 + 0] * ac + lin2srgb(accR) * omac;
            out[ind * 3 + 1] = grd_rgb[ind * 3 + 1] * ac + lin2srgb(accG) * omac;
            out[ind * 3 + 2] = grd_rgb[ind * 3 + 2] * ac + lin2srgb(accB) * omac;
        }
    }
}

// ---------------------------------------------------------------------------
extern "C" void kernel_launch(void* const* d_in, const int* in_sizes, int n_in,
                              void* d_out, int out_size)
{
    const float* surf     = (const float*)d_in[0];
    const float* ray_o    = (const float*)d_in[1];
    const float* norm_raw = (const float*)d_in[2];
    const float* albedo   = (const float*)d_in[3];
    const float* rough    = (const float*)d_in[4];
    const float* lvis     = (const float*)d_in[5];
    const float* xyz      = (const float*)d_in[6];
    const float* area     = (const float*)d_in[7];
    const float* probe    = (const float*)d_in[8];
    const float* grd_rgb  = (const float*)d_in[9];
    const float* grd_acc  = (const float*)d_in[10];
    const int*   inds     = (const int*)  d_in[11];
    float* out = (float*)d_out;

    const int P  = in_sizes[11];   // 8192 points
    const int n3 = out_size;       // 65536*3

    base_merge_kernel<<<(n3 + 255) / 256, 256>>>(grd_rgb, grd_acc, out, n3);

    const int warpsPerBlock = 8;
    const int blocks = (P + warpsPerBlock - 1) / warpsPerBlock;
    render_kernel<<<blocks, 256>>>(surf, ray_o, norm_raw, albedo, rough, lvis,
                                   xyz, area, probe, grd_rgb, grd_acc, inds,
                                   out, P);
}